// round 10
// baseline (speedup 1.0000x reference)
#include <cuda_runtime.h>
#include <cuda_fp16.h>
#include <stdint.h>
#include <math.h>

#define NN   50000
#define EE   800000
#define PP   3
#define INF_ 128
#define HH   8
#define DD   32
#define HD   256   // H*D
#define KTOT 768   // P*H*D
#define EMB  128
#define PN   (PP * NN)

// ---------------- scratch (static __device__; no allocations allowed) ---------
__device__ __half g_feat[PP * NN * HD];  // projected features (fp16)
__device__ float  g_out [PP * NN * HD];  // per-metapath GAT output (post-ELU)
__device__ float  g_el  [PP * NN * HH];
__device__ float  g_er  [PP * NN * HH];
__device__ int    g_deg   [PN];
__device__ int    g_offs  [PN + 1];
__device__ int    g_cursor[PN];
__device__ int    g_srcl  [PP * EE];     // CSR-ordered src node ids

// ---------------- mma helpers --------------------------------------------------
__device__ __forceinline__ float tf32f(float x) {
    uint32_t u; asm("cvt.rna.tf32.f32 %0, %1;" : "=r"(u) : "f"(x));
    return __uint_as_float(u);
}
__device__ __forceinline__ void mma8(float* d, const uint32_t* a, const uint32_t* b) {
    asm volatile("mma.sync.aligned.m16n8k8.row.col.f32.tf32.tf32.f32 "
                 "{%0,%1,%2,%3},{%4,%5,%6,%7},{%8,%9},{%0,%1,%2,%3};"
                 : "+f"(d[0]), "+f"(d[1]), "+f"(d[2]), "+f"(d[3])
                 : "r"(a[0]), "r"(a[1]), "r"(a[2]), "r"(a[3]), "r"(b[0]), "r"(b[1]));
}

// ---------------- zero degree counters ----------------------------------------
__global__ void k_zero() {
    int idx = blockIdx.x * 256 + threadIdx.x;
    if (idx < PN) g_deg[idx] = 0;
}

// ---------------- feat = h @ W_p via tf32 MMA, fp16 store ---------------------
__global__ void k_feat(const float* __restrict__ hin, const float* __restrict__ fcw)
{
    __shared__ float Hs[32][132];
    __shared__ float Ws[32][136];
    const int p  = blockIdx.y, ch = blockIdx.z;
    const int nb = blockIdx.x * 32;
    const int t  = threadIdx.x, warp = t >> 5, lane = t & 31;
    const int g  = lane >> 2, tg = lane & 3;
    const int rw = warp >> 2, cw = warp & 3;

    for (int i = t; i < 32 * 32; i += 256) {
        int r = i >> 5, q = i & 31;
        int row = nb + r;
        float4 v = make_float4(0.f, 0.f, 0.f, 0.f);
        if (row < NN) v = __ldcs((const float4*)(hin + row * INF_ + q * 4));
        v.x = tf32f(v.x); v.y = tf32f(v.y); v.z = tf32f(v.z); v.w = tf32f(v.w);
        *(float4*)&Hs[r][q * 4] = v;
    }

    float acc[4][4];
#pragma unroll
    for (int nt = 0; nt < 4; ++nt)
#pragma unroll
        for (int j = 0; j < 4; ++j) acc[nt][j] = 0.f;

    const float* Wbase = fcw + p * INF_ * HD + ch * 128;
    for (int kc = 0; kc < INF_; kc += 32) {
        __syncthreads();
        for (int i = t; i < 32 * 32; i += 256) {
            int kk = i >> 5, q = i & 31;
            float4 v = *(const float4*)(Wbase + (kc + kk) * HD + q * 4);
            v.x = tf32f(v.x); v.y = tf32f(v.y); v.z = tf32f(v.z); v.w = tf32f(v.w);
            *(float4*)&Ws[kk][q * 4] = v;
        }
        __syncthreads();
#pragma unroll
        for (int ks = 0; ks < 4; ++ks) {
            uint32_t a[4];
            const int arow = rw * 16 + g, acol = kc + ks * 8 + tg;
            a[0] = __float_as_uint(Hs[arow][acol]);
            a[1] = __float_as_uint(Hs[arow + 8][acol]);
            a[2] = __float_as_uint(Hs[arow][acol + 4]);
            a[3] = __float_as_uint(Hs[arow + 8][acol + 4]);
#pragma unroll
            for (int nt = 0; nt < 4; ++nt) {
                uint32_t b[2];
                const int bcol = cw * 32 + nt * 8 + g;
                b[0] = __float_as_uint(Ws[ks * 8 + tg][bcol]);
                b[1] = __float_as_uint(Ws[ks * 8 + tg + 4][bcol]);
                mma8(acc[nt], a, b);
            }
        }
    }

    const int row0 = nb + rw * 16 + g, row1 = row0 + 8;
    __half* fp = g_feat + (long)p * NN * HD + ch * 128;
#pragma unroll
    for (int nt = 0; nt < 4; ++nt) {
        const int col = cw * 32 + nt * 8 + 2 * tg;
        if (row0 < NN)
            *(__half2*)(fp + (long)row0 * HD + col) = __floats2half2_rn(acc[nt][0], acc[nt][1]);
        if (row1 < NN)
            *(__half2*)(fp + (long)row1 * HD + col) = __floats2half2_rn(acc[nt][2], acc[nt][3]);
    }
}

// ---------------- el/er from fp16 feat ----------------------------------------
__global__ void k_elr(const float* __restrict__ al, const float* __restrict__ ar)
{
    const int wid = threadIdx.x >> 5, lane = threadIdx.x & 31;
    const int pn = blockIdx.x * 8 + wid;
    const int p  = pn / NN;
    const uint4 v = *((const uint4*)(g_feat + (long)pn * HD) + lane);
    const __half2* hv = (const __half2*)&v;
    const int head = lane >> 2, dbase = (lane & 3) * 8;
    const float* alp = al + p * HH * DD + head * DD + dbase;
    const float* arp = ar + p * HH * DD + head * DD + dbase;
    float sl = 0.f, sr = 0.f;
#pragma unroll
    for (int j = 0; j < 4; ++j) {
        float2 f = __half22float2(hv[j]);
        sl += f.x * alp[2 * j] + f.y * alp[2 * j + 1];
        sr += f.x * arp[2 * j] + f.y * arp[2 * j + 1];
    }
    sl += __shfl_xor_sync(0xffffffffu, sl, 1);
    sl += __shfl_xor_sync(0xffffffffu, sl, 2);
    sr += __shfl_xor_sync(0xffffffffu, sr, 1);
    sr += __shfl_xor_sync(0xffffffffu, sr, 2);
    if ((lane & 3) == 0) {
        g_el[pn * HH + head] = sl;
        g_er[pn * HH + head] = sr;
    }
}

// ---------------- CSR build ----------------------------------------------------
__global__ void k_hist(const int* __restrict__ ei) {
    const int p = blockIdx.y;
    const int e = blockIdx.x * 256 + threadIdx.x;
    const int dst = ei[p * 2 * EE + EE + e];
    atomicAdd(&g_deg[p * NN + dst], 1);
}

#define CHUNK 147   // ceil(150000 / 1024)
__global__ void k_scan() {
    __shared__ int s[1024];
    const int t = threadIdx.x;
    const int base = t * CHUNK;
    int sum = 0;
    for (int j = 0; j < CHUNK; ++j) {
        int idx = base + j;
        if (idx < PN) sum += g_deg[idx];
    }
    s[t] = sum;
    __syncthreads();
    for (int o = 1; o < 1024; o <<= 1) {
        int v = (t >= o) ? s[t - o] : 0;
        __syncthreads();
        s[t] += v;
        __syncthreads();
    }
    int run = (t > 0) ? s[t - 1] : 0;
    for (int j = 0; j < CHUNK; ++j) {
        int idx = base + j;
        if (idx < PN) {
            g_offs[idx]   = run;
            g_cursor[idx] = run;
            run += g_deg[idx];
        }
    }
    if (t == 1023) g_offs[PN] = s[1023];
}

__global__ void k_scatter(const int* __restrict__ ei) {
    const int p = blockIdx.y;
    const int e = blockIdx.x * 256 + threadIdx.x;
    const int src = ei[p * 2 * EE + e];
    const int dst = ei[p * 2 * EE + EE + e];
    int pos = atomicAdd(&g_cursor[p * NN + dst], 1);
    g_srcl[pos] = src;
}

// ---------------- per-dst gather-aggregate + softmax + ELU (fused) ------------
// ONE metapath per launch: the 25.6 MB feat slice stays L2-resident instead of
// three slices (77 MB) + out-writes thrashing L2 to DRAM. Streaming stores for
// g_out keep write allocations from evicting feat lines.
__global__ void k_agg(int p)
{
    const int wid  = threadIdx.x >> 5;
    const int lane = threadIdx.x & 31;
    const int n    = blockIdx.x * 8 + wid;
    const int pn   = p * NN + n;
    const int hh   = lane >> 2;
    const float er_h = g_er[pn * HH + hh];

    const int beg = g_offs[pn];
    const int end = g_offs[pn + 1];

    float a[8];
#pragma unroll
    for (int j = 0; j < 8; ++j) a[j] = 0.f;
    float den = 0.f;
    const uint4* fb = (const uint4*)g_feat;

    int i = beg;
    for (; i + 4 <= end; i += 4) {
        const int b0 = p * NN + __ldg(&g_srcl[i]);
        const int b1 = p * NN + __ldg(&g_srcl[i + 1]);
        const int b2 = p * NN + __ldg(&g_srcl[i + 2]);
        const int b3 = p * NN + __ldg(&g_srcl[i + 3]);
        const float x0 = __ldg(&g_el[b0 * HH + hh]);
        const float x1 = __ldg(&g_el[b1 * HH + hh]);
        const float x2 = __ldg(&g_el[b2 * HH + hh]);
        const float x3 = __ldg(&g_el[b3 * HH + hh]);
        const uint4 v0 = __ldg(&fb[b0 * 32 + lane]);
        const uint4 v1 = __ldg(&fb[b1 * 32 + lane]);
        const uint4 v2 = __ldg(&fb[b2 * 32 + lane]);
        const uint4 v3 = __ldg(&fb[b3 * 32 + lane]);
        float y0 = x0 + er_h, y1 = x1 + er_h, y2 = x2 + er_h, y3 = x3 + er_h;
        const float ex0 = __expf(fmaxf(y0, 0.2f * y0));
        const float ex1 = __expf(fmaxf(y1, 0.2f * y1));
        const float ex2 = __expf(fmaxf(y2, 0.2f * y2));
        const float ex3 = __expf(fmaxf(y3, 0.2f * y3));
        den += (ex0 + ex1) + (ex2 + ex3);
        const __half2* h0 = (const __half2*)&v0;
        const __half2* h1 = (const __half2*)&v1;
        const __half2* h2 = (const __half2*)&v2;
        const __half2* h3 = (const __half2*)&v3;
#pragma unroll
        for (int j = 0; j < 4; ++j) {
            float2 f0 = __half22float2(h0[j]);
            float2 f1 = __half22float2(h1[j]);
            float2 f2 = __half22float2(h2[j]);
            float2 f3 = __half22float2(h3[j]);
            a[2 * j]     = fmaf(ex0, f0.x, fmaf(ex1, f1.x, fmaf(ex2, f2.x, fmaf(ex3, f3.x, a[2 * j]))));
            a[2 * j + 1] = fmaf(ex0, f0.y, fmaf(ex1, f1.y, fmaf(ex2, f2.y, fmaf(ex3, f3.y, a[2 * j + 1]))));
        }
    }
    for (; i < end; ++i) {
        const int b0 = p * NN + __ldg(&g_srcl[i]);
        const float x0 = __ldg(&g_el[b0 * HH + hh]) + er_h;
        const uint4 v0 = __ldg(&fb[b0 * 32 + lane]);
        const float ex0 = __expf(fmaxf(x0, 0.2f * x0));
        den += ex0;
        const __half2* h0 = (const __half2*)&v0;
#pragma unroll
        for (int j = 0; j < 4; ++j) {
            float2 f0 = __half22float2(h0[j]);
            a[2 * j]     = fmaf(ex0, f0.x, a[2 * j]);
            a[2 * j + 1] = fmaf(ex0, f0.y, a[2 * j + 1]);
        }
    }

    const float inv = den > 0.f ? 1.f / den : 0.f;
#pragma unroll
    for (int j = 0; j < 8; ++j) {
        float v = a[j] * inv;
        a[j] = v > 0.f ? v : expm1f(v);
    }
    float4* op = (float4*)(g_out + (long)pn * HD + lane * 8);
    __stcs(op,     make_float4(a[0], a[1], a[2], a[3]));
    __stcs(op + 1, make_float4(a[4], a[5], a[6], a[7]));
}

// ---------------- final: out = z @ sem_w + sem_b via tf32 MMA -----------------
__global__ void k_sem(const float* __restrict__ sw, const float* __restrict__ sb,
                      float* __restrict__ out)
{
    __shared__ float Zs[128][36];
    __shared__ float Ws[32][136];
    const int nb = blockIdx.x * 128;
    const int t  = threadIdx.x, warp = t >> 5, lane = t & 31;
    const int g  = lane >> 2, tg = lane & 3;
    const int rw = warp >> 1, cw = warp & 1;

    float acc[2][8][4];
#pragma unroll
    for (int mt = 0; mt < 2; ++mt)
#pragma unroll
        for (int nt = 0; nt < 8; ++nt)
#pragma unroll
            for (int j = 0; j < 4; ++j) acc[mt][nt][j] = 0.f;

    for (int k0 = 0; k0 < KTOT; k0 += 32) {
        const int p  = k0 >> 8;
        const int c0 = k0 & 255;
        __syncthreads();
        for (int i = t; i < 1024; i += 256) {
            int r = i >> 3, q = i & 7;
            int row = nb + r;
            float4 v = make_float4(0.f, 0.f, 0.f, 0.f);
            if (row < NN)
                v = __ldcs((const float4*)(g_out + ((long)p * NN + row) * HD + c0 + q * 4));
            v.x = tf32f(v.x); v.y = tf32f(v.y); v.z = tf32f(v.z); v.w = tf32f(v.w);
            *(float4*)&Zs[r][q * 4] = v;
        }
        for (int i = t; i < 1024; i += 256) {
            int kk = i >> 5, q = i & 31;
            float4 v = *(const float4*)(sw + (long)(k0 + kk) * EMB + q * 4);
            v.x = tf32f(v.x); v.y = tf32f(v.y); v.z = tf32f(v.z); v.w = tf32f(v.w);
            *(float4*)&Ws[kk][q * 4] = v;
        }
        __syncthreads();
#pragma unroll
        for (int ks = 0; ks < 4; ++ks) {
            uint32_t a[2][4];
#pragma unroll
            for (int mt = 0; mt < 2; ++mt) {
                const int arow = rw * 32 + mt * 16 + g, acol = ks * 8 + tg;
                a[mt][0] = __float_as_uint(Zs[arow][acol]);
                a[mt][1] = __float_as_uint(Zs[arow + 8][acol]);
                a[mt][2] = __float_as_uint(Zs[arow][acol + 4]);
                a[mt][3] = __float_as_uint(Zs[arow + 8][acol + 4]);
            }
#pragma unroll
            for (int nt = 0; nt < 8; ++nt) {
                uint32_t b[2];
                const int bcol = cw * 64 + nt * 8 + g;
                b[0] = __float_as_uint(Ws[ks * 8 + tg][bcol]);
                b[1] = __float_as_uint(Ws[ks * 8 + tg + 4][bcol]);
                mma8(acc[0][nt], a[0], b);
                mma8(acc[1][nt], a[1], b);
            }
        }
    }

#pragma unroll
    for (int mt = 0; mt < 2; ++mt) {
        const int row0 = nb + rw * 32 + mt * 16 + g, row1 = row0 + 8;
#pragma unroll
        for (int nt = 0; nt < 8; ++nt) {
            const int col = cw * 64 + nt * 8 + 2 * tg;
            const float b0v = sb[col], b1v = sb[col + 1];
            if (row0 < NN) {
                out[(long)row0 * EMB + col]     = acc[mt][nt][0] + b0v;
                out[(long)row0 * EMB + col + 1] = acc[mt][nt][1] + b1v;
            }
            if (row1 < NN) {
                out[(long)row1 * EMB + col]     = acc[mt][nt][2] + b0v;
                out[(long)row1 * EMB + col + 1] = acc[mt][nt][3] + b1v;
            }
        }
    }
}

// ---------------- launch ------------------------------------------------------
extern "C" void kernel_launch(void* const* d_in, const int* in_sizes, int n_in,
                              void* d_out, int out_size)
{
    const float* h   = (const float*)d_in[0];
    const int*   ei  = (const int*)  d_in[1];
    const float* fcw = (const float*)d_in[2];
    const float* al  = (const float*)d_in[3];
    const float* ar  = (const float*)d_in[4];
    const float* sw  = (const float*)d_in[5];
    const float* sb  = (const float*)d_in[6];
    float* out = (float*)d_out;

    k_zero   <<<(PN + 255) / 256, 256>>>();
    k_hist   <<<dim3(EE / 256, PP), 256>>>(ei);
    k_scan   <<<1, 1024>>>();
    k_scatter<<<dim3(EE / 256, PP), 256>>>(ei);
    k_feat   <<<dim3((NN + 31) / 32, PP, 2), 256>>>(h, fcw);
    k_elr    <<<PN / 8, 256>>>(al, ar);
    k_agg    <<<NN / 8, 256>>>(0);
    k_agg    <<<NN / 8, 256>>>(1);
    k_agg    <<<NN / 8, 256>>>(2);
    k_sem    <<<(NN + 127) / 128, 256>>>(sw, sb, out);
}

// round 11
// speedup vs baseline: 1.0960x; 1.0960x over previous
#include <cuda_runtime.h>
#include <cuda_fp16.h>
#include <stdint.h>
#include <math.h>

#define NN   50000
#define EE   800000
#define PP   3
#define INF_ 128
#define HH   8
#define DD   32
#define HD   256   // H*D
#define KTOT 768   // P*H*D
#define EMB  128
#define PN   (PP * NN)

// ---------------- scratch (static __device__; no allocations allowed) ---------
__device__ __half g_h16 [NN * INF_];      // h in fp16
__device__ __half g_fcwh[PP * INF_ * HD]; // fc weights fp16
__device__ __half g_swh [KTOT * EMB];     // sem weights fp16
__device__ __half g_feat[PP * NN * HD];   // projected features (fp16)
__device__ __half g_outh[PP * NN * HD];   // per-metapath GAT output (fp16, post-ELU)
__device__ float  g_el  [PP * NN * HH];
__device__ float  g_er  [PP * NN * HH];
__device__ int    g_deg   [PN];
__device__ int    g_offs  [PN + 1];
__device__ int    g_cursor[PN];
__device__ int    g_srcl  [PP * EE];      // CSR-ordered src node ids

// ---------------- fp16 mma (m16n8k16, fp32 accum) ------------------------------
__device__ __forceinline__ void mma16(float* d, const uint32_t* a, const uint32_t* b) {
    asm volatile("mma.sync.aligned.m16n8k16.row.col.f32.f16.f16.f32 "
                 "{%0,%1,%2,%3},{%4,%5,%6,%7},{%8,%9},{%0,%1,%2,%3};"
                 : "+f"(d[0]), "+f"(d[1]), "+f"(d[2]), "+f"(d[3])
                 : "r"(a[0]), "r"(a[1]), "r"(a[2]), "r"(a[3]), "r"(b[0]), "r"(b[1]));
}

// ---------------- input conversions --------------------------------------------
__global__ void k_hconv(const float* __restrict__ hin) {
    int idx = blockIdx.x * 256 + threadIdx.x;   // one float4 each
    if (idx < NN * INF_ / 4) {
        float4 v = ((const float4*)hin)[idx];
        ((__half2*)g_h16)[idx * 2]     = __floats2half2_rn(v.x, v.y);
        ((__half2*)g_h16)[idx * 2 + 1] = __floats2half2_rn(v.z, v.w);
    }
}
__global__ void k_wconv(const float* __restrict__ fcw, const float* __restrict__ sw) {
    int idx = blockIdx.x * 256 + threadIdx.x;
    if (idx < 24576) {                       // fcw: 98304 elems = 24576 float4
        float4 v = ((const float4*)fcw)[idx];
        ((__half2*)g_fcwh)[idx * 2]     = __floats2half2_rn(v.x, v.y);
        ((__half2*)g_fcwh)[idx * 2 + 1] = __floats2half2_rn(v.z, v.w);
    } else if (idx < 49152) {                // sw: 98304 elems
        int j = idx - 24576;
        float4 v = ((const float4*)sw)[j];
        ((__half2*)g_swh)[j * 2]     = __floats2half2_rn(v.x, v.y);
        ((__half2*)g_swh)[j * 2 + 1] = __floats2half2_rn(v.z, v.w);
    }
}

// ---------------- zero degree counters ----------------------------------------
__global__ void k_zero() {
    int idx = blockIdx.x * 256 + threadIdx.x;
    if (idx < PN) g_deg[idx] = 0;
}

// ---------------- feat = h @ W_p via fp16 MMA ---------------------------------
// CTA tile 32 rows x 128 cols (blockIdx.z = col half). 8 warps (2 m x 4 n),
// warp tile 16x32. Full W tile (128k x 128n) staged transposed in smem.
__global__ void k_feat()
{
    __shared__ __half Hs[32][136];    // [m][k], stride 68 words: frag reads conflict-free
    __shared__ __half Wt[128][136];   // [n][k] transposed
    const int p  = blockIdx.y, ch = blockIdx.z;
    const int nb = blockIdx.x * 32;
    const int t  = threadIdx.x, warp = t >> 5, lane = t & 31;
    const int g  = lane >> 2, tg = lane & 3;
    const int rw = warp >> 2, cw = warp & 3;

    // Hs: 32 x 128 halfs = 512 uint4
    for (int i = t; i < 512; i += 256) {
        int r = i >> 4, q = i & 15;
        int row = nb + r;
        uint4 v = make_uint4(0u, 0u, 0u, 0u);
        if (row < NN) v = *(const uint4*)(g_h16 + (long)row * INF_ + q * 8);
        *(uint4*)&Hs[r][q * 8] = v;
    }
    // Wt: transpose 128k x 128n
    const __half* Wbase = g_fcwh + p * INF_ * HD + ch * 128;
    for (int i = t; i < 128 * 128; i += 256) {
        int k = i >> 7, c = i & 127;
        Wt[c][k] = Wbase[k * HD + c];
    }
    __syncthreads();

    float acc[4][4];
#pragma unroll
    for (int nt = 0; nt < 4; ++nt)
#pragma unroll
        for (int j = 0; j < 4; ++j) acc[nt][j] = 0.f;

#pragma unroll
    for (int ks = 0; ks < 8; ++ks) {
        const int k0 = ks * 16;
        uint32_t a[4];
        a[0] = *(const uint32_t*)&Hs[rw * 16 + g][k0 + 2 * tg];
        a[1] = *(const uint32_t*)&Hs[rw * 16 + 8 + g][k0 + 2 * tg];
        a[2] = *(const uint32_t*)&Hs[rw * 16 + g][k0 + 8 + 2 * tg];
        a[3] = *(const uint32_t*)&Hs[rw * 16 + 8 + g][k0 + 8 + 2 * tg];
#pragma unroll
        for (int nt = 0; nt < 4; ++nt) {
            const int bcol = cw * 32 + nt * 8 + g;
            uint32_t b[2];
            b[0] = *(const uint32_t*)&Wt[bcol][k0 + 2 * tg];
            b[1] = *(const uint32_t*)&Wt[bcol][k0 + 8 + 2 * tg];
            mma16(acc[nt], a, b);
        }
    }

    const int row0 = nb + rw * 16 + g, row1 = row0 + 8;
    __half* fp = g_feat + (long)p * NN * HD + ch * 128;
#pragma unroll
    for (int nt = 0; nt < 4; ++nt) {
        const int col = cw * 32 + nt * 8 + 2 * tg;
        if (row0 < NN)
            *(__half2*)(fp + (long)row0 * HD + col) = __floats2half2_rn(acc[nt][0], acc[nt][1]);
        if (row1 < NN)
            *(__half2*)(fp + (long)row1 * HD + col) = __floats2half2_rn(acc[nt][2], acc[nt][3]);
    }
}

// ---------------- el/er from fp16 feat ----------------------------------------
__global__ void k_elr(const float* __restrict__ al, const float* __restrict__ ar)
{
    const int wid = threadIdx.x >> 5, lane = threadIdx.x & 31;
    const int pn = blockIdx.x * 8 + wid;
    const int p  = pn / NN;
    const uint4 v = *((const uint4*)(g_feat + (long)pn * HD) + lane);
    const __half2* hv = (const __half2*)&v;
    const int head = lane >> 2, dbase = (lane & 3) * 8;
    const float* alp = al + p * HH * DD + head * DD + dbase;
    const float* arp = ar + p * HH * DD + head * DD + dbase;
    float sl = 0.f, sr = 0.f;
#pragma unroll
    for (int j = 0; j < 4; ++j) {
        float2 f = __half22float2(hv[j]);
        sl += f.x * alp[2 * j] + f.y * alp[2 * j + 1];
        sr += f.x * arp[2 * j] + f.y * arp[2 * j + 1];
    }
    sl += __shfl_xor_sync(0xffffffffu, sl, 1);
    sl += __shfl_xor_sync(0xffffffffu, sl, 2);
    sr += __shfl_xor_sync(0xffffffffu, sr, 1);
    sr += __shfl_xor_sync(0xffffffffu, sr, 2);
    if ((lane & 3) == 0) {
        g_el[pn * HH + head] = sl;
        g_er[pn * HH + head] = sr;
    }
}

// ---------------- CSR build ----------------------------------------------------
__global__ void k_hist(const int* __restrict__ ei) {
    const int p = blockIdx.y;
    const int e = blockIdx.x * 256 + threadIdx.x;
    const int dst = ei[p * 2 * EE + EE + e];
    atomicAdd(&g_deg[p * NN + dst], 1);
}

#define CHUNK 147   // ceil(150000 / 1024)
__global__ void k_scan() {
    __shared__ int s[1024];
    const int t = threadIdx.x;
    const int base = t * CHUNK;
    int sum = 0;
    for (int j = 0; j < CHUNK; ++j) {
        int idx = base + j;
        if (idx < PN) sum += g_deg[idx];
    }
    s[t] = sum;
    __syncthreads();
    for (int o = 1; o < 1024; o <<= 1) {
        int v = (t >= o) ? s[t - o] : 0;
        __syncthreads();
        s[t] += v;
        __syncthreads();
    }
    int run = (t > 0) ? s[t - 1] : 0;
    for (int j = 0; j < CHUNK; ++j) {
        int idx = base + j;
        if (idx < PN) {
            g_offs[idx]   = run;
            g_cursor[idx] = run;
            run += g_deg[idx];
        }
    }
    if (t == 1023) g_offs[PN] = s[1023];
}

__global__ void k_scatter(const int* __restrict__ ei) {
    const int p = blockIdx.y;
    const int e = blockIdx.x * 256 + threadIdx.x;
    const int src = ei[p * 2 * EE + e];
    const int dst = ei[p * 2 * EE + EE + e];
    int pos = atomicAdd(&g_cursor[p * NN + dst], 1);
    g_srcl[pos] = src;
}

// ---------------- per-dst gather-aggregate + softmax + ELU (fused) ------------
__global__ void k_agg(int p)
{
    const int wid  = threadIdx.x >> 5;
    const int lane = threadIdx.x & 31;
    const int n    = blockIdx.x * 8 + wid;
    const int pn   = p * NN + n;
    const int hh   = lane >> 2;
    const float er_h = g_er[pn * HH + hh];

    const int beg = g_offs[pn];
    const int end = g_offs[pn + 1];

    float a[8];
#pragma unroll
    for (int j = 0; j < 8; ++j) a[j] = 0.f;
    float den = 0.f;
    const uint4* fb = (const uint4*)g_feat;

    int i = beg;
    for (; i + 4 <= end; i += 4) {
        const int b0 = p * NN + __ldg(&g_srcl[i]);
        const int b1 = p * NN + __ldg(&g_srcl[i + 1]);
        const int b2 = p * NN + __ldg(&g_srcl[i + 2]);
        const int b3 = p * NN + __ldg(&g_srcl[i + 3]);
        const float x0 = __ldg(&g_el[b0 * HH + hh]);
        const float x1 = __ldg(&g_el[b1 * HH + hh]);
        const float x2 = __ldg(&g_el[b2 * HH + hh]);
        const float x3 = __ldg(&g_el[b3 * HH + hh]);
        const uint4 v0 = __ldg(&fb[b0 * 32 + lane]);
        const uint4 v1 = __ldg(&fb[b1 * 32 + lane]);
        const uint4 v2 = __ldg(&fb[b2 * 32 + lane]);
        const uint4 v3 = __ldg(&fb[b3 * 32 + lane]);
        float y0 = x0 + er_h, y1 = x1 + er_h, y2 = x2 + er_h, y3 = x3 + er_h;
        const float ex0 = __expf(fmaxf(y0, 0.2f * y0));
        const float ex1 = __expf(fmaxf(y1, 0.2f * y1));
        const float ex2 = __expf(fmaxf(y2, 0.2f * y2));
        const float ex3 = __expf(fmaxf(y3, 0.2f * y3));
        den += (ex0 + ex1) + (ex2 + ex3);
        const __half2* h0 = (const __half2*)&v0;
        const __half2* h1 = (const __half2*)&v1;
        const __half2* h2 = (const __half2*)&v2;
        const __half2* h3 = (const __half2*)&v3;
#pragma unroll
        for (int j = 0; j < 4; ++j) {
            float2 f0 = __half22float2(h0[j]);
            float2 f1 = __half22float2(h1[j]);
            float2 f2 = __half22float2(h2[j]);
            float2 f3 = __half22float2(h3[j]);
            a[2 * j]     = fmaf(ex0, f0.x, fmaf(ex1, f1.x, fmaf(ex2, f2.x, fmaf(ex3, f3.x, a[2 * j]))));
            a[2 * j + 1] = fmaf(ex0, f0.y, fmaf(ex1, f1.y, fmaf(ex2, f2.y, fmaf(ex3, f3.y, a[2 * j + 1]))));
        }
    }
    for (; i < end; ++i) {
        const int b0 = p * NN + __ldg(&g_srcl[i]);
        const float x0 = __ldg(&g_el[b0 * HH + hh]) + er_h;
        const uint4 v0 = __ldg(&fb[b0 * 32 + lane]);
        const float ex0 = __expf(fmaxf(x0, 0.2f * x0));
        den += ex0;
        const __half2* h0 = (const __half2*)&v0;
#pragma unroll
        for (int j = 0; j < 4; ++j) {
            float2 f0 = __half22float2(h0[j]);
            a[2 * j]     = fmaf(ex0, f0.x, a[2 * j]);
            a[2 * j + 1] = fmaf(ex0, f0.y, a[2 * j + 1]);
        }
    }

    const float inv = den > 0.f ? 1.f / den : 0.f;
#pragma unroll
    for (int j = 0; j < 8; ++j) {
        float v = a[j] * inv;
        a[j] = v > 0.f ? v : expm1f(v);
    }
    uint4 pk;
    __half2* ph = (__half2*)&pk;
    ph[0] = __floats2half2_rn(a[0], a[1]);
    ph[1] = __floats2half2_rn(a[2], a[3]);
    ph[2] = __floats2half2_rn(a[4], a[5]);
    ph[3] = __floats2half2_rn(a[6], a[7]);
    __stcs((uint4*)(g_outh + (long)pn * HD + lane * 8), pk);
}

// ---------------- final: out = z @ sem_w + sem_b via fp16 MMA -----------------
// CTA tile 128x128, K=768 in 24 chunks of 32 (2 ksteps each). 8 warps (4x2),
// warp tile 32x64.
__global__ void k_sem(const float* __restrict__ sb, float* __restrict__ out)
{
    __shared__ __half Zs[128][40];    // [m][k]
    __shared__ __half Wt[128][40];    // [n][k] transposed
    const int nb = blockIdx.x * 128;
    const int t  = threadIdx.x, warp = t >> 5, lane = t & 31;
    const int g  = lane >> 2, tg = lane & 3;
    const int rw = warp >> 1, cw = warp & 1;

    float acc[2][8][4];
#pragma unroll
    for (int mt = 0; mt < 2; ++mt)
#pragma unroll
        for (int nt = 0; nt < 8; ++nt)
#pragma unroll
            for (int j = 0; j < 4; ++j) acc[mt][nt][j] = 0.f;

    for (int k0 = 0; k0 < KTOT; k0 += 32) {
        const int p  = k0 >> 8;
        const int c0 = k0 & 255;
        __syncthreads();
        // Zs: 128 rows x 32 halfs = 512 uint4
        for (int i = t; i < 512; i += 256) {
            int r = i >> 2, q = i & 3;
            int row = nb + r;
            uint4 v = make_uint4(0u, 0u, 0u, 0u);
            if (row < NN)
                v = __ldcs((const uint4*)(g_outh + ((long)p * NN + row) * HD + c0 + q * 8));
            *(uint4*)&Zs[r][q * 8] = v;
        }
        // Wt: transpose 32k x 128n
        for (int i = t; i < 32 * 128; i += 256) {
            int kk = i >> 7, c = i & 127;
            Wt[c][kk] = g_swh[(long)(k0 + kk) * EMB + c];
        }
        __syncthreads();
#pragma unroll
        for (int ks = 0; ks < 2; ++ks) {
            const int kb = ks * 16;
            uint32_t a[2][4];
#pragma unroll
            for (int mt = 0; mt < 2; ++mt) {
                const int arow = rw * 32 + mt * 16 + g;
                a[mt][0] = *(const uint32_t*)&Zs[arow][kb + 2 * tg];
                a[mt][1] = *(const uint32_t*)&Zs[arow + 8][kb + 2 * tg];
                a[mt][2] = *(const uint32_t*)&Zs[arow][kb + 8 + 2 * tg];
                a[mt][3] = *(const uint32_t*)&Zs[arow + 8][kb + 8 + 2 * tg];
            }
#pragma unroll
            for (int nt = 0; nt < 8; ++nt) {
                const int bcol = cw * 64 + nt * 8 + g;
                uint32_t b[2];
                b[0] = *(const uint32_t*)&Wt[bcol][kb + 2 * tg];
                b[1] = *(const uint32_t*)&Wt[bcol][kb + 8 + 2 * tg];
                mma16(acc[0][nt], a[0], b);
                mma16(acc[1][nt], a[1], b);
            }
        }
    }

#pragma unroll
    for (int mt = 0; mt < 2; ++mt) {
        const int row0 = nb + rw * 32 + mt * 16 + g, row1 = row0 + 8;
#pragma unroll
        for (int nt = 0; nt < 8; ++nt) {
            const int col = cw * 64 + nt * 8 + 2 * tg;
            const float b0v = sb[col], b1v = sb[col + 1];
            if (row0 < NN) {
                out[(long)row0 * EMB + col]     = acc[mt][nt][0] + b0v;
                out[(long)row0 * EMB + col + 1] = acc[mt][nt][1] + b1v;
            }
            if (row1 < NN) {
                out[(long)row1 * EMB + col]     = acc[mt][nt][2] + b0v;
                out[(long)row1 * EMB + col + 1] = acc[mt][nt][3] + b1v;
            }
        }
    }
}

// ---------------- launch ------------------------------------------------------
extern "C" void kernel_launch(void* const* d_in, const int* in_sizes, int n_in,
                              void* d_out, int out_size)
{
    const float* h   = (const float*)d_in[0];
    const int*   ei  = (const int*)  d_in[1];
    const float* fcw = (const float*)d_in[2];
    const float* al  = (const float*)d_in[3];
    const float* ar  = (const float*)d_in[4];
    const float* sw  = (const float*)d_in[5];
    const float* sb  = (const float*)d_in[6];
    float* out = (float*)d_out;

    k_hconv  <<<NN * INF_ / 4 / 256, 256>>>(h);          // 1
    k_wconv  <<<192, 256>>>(fcw, sw);                    // 2
    k_zero   <<<(PN + 255) / 256, 256>>>();              // 3
    k_feat   <<<dim3((NN + 31) / 32, PP, 2), 256>>>();   // 4  <- profiled slot
    k_hist   <<<dim3(EE / 256, PP), 256>>>(ei);          // 5
    k_scan   <<<1, 1024>>>();                            // 6
    k_scatter<<<dim3(EE / 256, PP), 256>>>(ei);          // 7
    k_elr    <<<PN / 8, 256>>>(al, ar);                  // 8
    k_agg    <<<NN / 8, 256>>>(0);                       // 9
    k_agg    <<<NN / 8, 256>>>(1);                       // 10
    k_agg    <<<NN / 8, 256>>>(2);                       // 11
    k_sem    <<<(NN + 127) / 128, 256>>>(sb, out);       // 12
}